// round 2
// baseline (speedup 1.0000x reference)
#include <cuda_runtime.h>

#define B_TOTAL 16384
#define NSTEPS  196

// Scratch (allocation-free: __device__ globals)
__device__ float g_xT[784 * B_TOTAL];   // transposed input: [pixel][batch]
__device__ float g_w1T[NSTEPS * 4 * 20]; // fc1 weights relaid: [(s*4+w)*20 + o]

// ---------------------------------------------------------------------------
// Kernel 1: transpose x (B,784) -> xT (784,B), coalesced both sides
// ---------------------------------------------------------------------------
__global__ void transpose_kernel(const float* __restrict__ x) {
    __shared__ float tile[32][33];
    const int bBase = blockIdx.x * 32;
    const int pBase = blockIdx.y * 32;
    const int tx = threadIdx.x, ty = threadIdx.y;
    #pragma unroll
    for (int k = 0; k < 4; k++) {
        int bb = bBase + ty + k * 8;
        int pp = pBase + tx;
        float v = 0.f;
        if (pp < 784) v = x[bb * 784 + pp];
        tile[ty + k * 8][tx] = v;
    }
    __syncthreads();
    #pragma unroll
    for (int k = 0; k < 4; k++) {
        int pp = pBase + ty + k * 8;
        int bb = bBase + tx;
        if (pp < 784) g_xT[pp * B_TOTAL + bb] = tile[tx][ty + k * 8];
    }
}

// ---------------------------------------------------------------------------
// Kernel 2: relay fc1_w (20,784) -> g_w1T[p*20+o] = fc1_w[o*784+p]
// ---------------------------------------------------------------------------
__global__ void w1t_kernel(const float* __restrict__ fc1_w) {
    int idx = blockIdx.x * blockDim.x + threadIdx.x;
    if (idx < 784 * 20) {
        int p = idx / 20, o = idx % 20;
        g_w1T[idx] = fc1_w[o * 784 + p];
    }
}

// ---------------------------------------------------------------------------
// Helpers: left-multiply 2x2 complex U by RY / RZ
// ---------------------------------------------------------------------------
__device__ __forceinline__ void ry_left(float c, float sn,
    float& u00r, float& u00i, float& u01r, float& u01i,
    float& u10r, float& u10i, float& u11r, float& u11i)
{
    float n00r = c * u00r - sn * u10r, n00i = c * u00i - sn * u10i;
    float n01r = c * u01r - sn * u11r, n01i = c * u01i - sn * u11i;
    float n10r = sn * u00r + c * u10r, n10i = sn * u00i + c * u10i;
    float n11r = sn * u01r + c * u11r, n11i = sn * u01i + c * u11i;
    u00r = n00r; u00i = n00i; u01r = n01r; u01i = n01i;
    u10r = n10r; u10i = n10i; u11r = n11r; u11i = n11i;
}

__device__ __forceinline__ void rz_left(float c, float sn,
    float& u00r, float& u00i, float& u01r, float& u01i,
    float& u10r, float& u10i, float& u11r, float& u11i)
{
    // row0 *= (c - i s); row1 *= (c + i s)
    float r_;
    r_ = c * u00r + sn * u00i; u00i = c * u00i - sn * u00r; u00r = r_;
    r_ = c * u01r + sn * u01i; u01i = c * u01i - sn * u01r; u01r = r_;
    r_ = c * u10r - sn * u10i; u10i = c * u10i + sn * u10r; u10r = r_;
    r_ = c * u11r - sn * u11i; u11i = c * u11i + sn * u11r; u11r = r_;
}

// ---------------------------------------------------------------------------
// Main kernel: one thread per batch element; state in registers.
// ---------------------------------------------------------------------------
__global__ __launch_bounds__(128, 1) void quanv_kernel(
    const float* __restrict__ crz_p, const float* __restrict__ ry_p,
    const float* __restrict__ fc1_b, const float* __restrict__ fc2_w,
    const float* __restrict__ fc2_b, float* __restrict__ out)
{
    const int b = blockIdx.x * 128 + threadIdx.x;
    const float RS = 0.7071067811865476f;

    // CRZ diagonal: exp(+0.5i * theta * sign[n]), sign from the ring pattern
    float crzr[16], crzi[16];
    {
        float th = __ldg(crz_p);
        #pragma unroll
        for (int n = 0; n < 16; n++) {
            int q0 = (n >> 3) & 1, q1 = (n >> 2) & 1, q2 = (n >> 1) & 1, q3 = n & 1;
            int sgn = q0 * (2 * q1 - 1) + q1 * (2 * q2 - 1)
                    + q2 * (2 * q3 - 1) + q3 * (2 * q0 - 1);
            float ang = 0.5f * th * (float)sgn;
            crzr[n] = __cosf(ang);
            crzi[n] = __sinf(ang);
        }
    }
    float ryt = __ldg(ry_p);
    const float cR = __cosf(0.5f * ryt), sR = __sinf(0.5f * ryt);

    // State |0000> ; carried across all 196 steps (lax.scan semantics)
    float Sr[16], Si[16];
    #pragma unroll
    for (int n = 0; n < 16; n++) { Sr[n] = 0.f; Si[n] = 0.f; }
    Sr[0] = 1.f;

    // Fused fc1 accumulators
    float h1[20];
    #pragma unroll
    for (int o = 0; o < 20; o++) h1[o] = __ldg(&fc1_b[o]);

    // Prefetch angles for step 0 (window i=0,j=0: full 4x4)
    float A[16];
    #pragma unroll
    for (int k = 0; k < 16; k++) {
        int r = k >> 2, c = k & 3;
        A[k] = g_xT[(r * 28 + c) * B_TOTAL + b];
    }

    int wi = 0, wj = 0;
    #pragma unroll 1
    for (int s = 0; s < NSTEPS; s++) {
        // ---- prefetch next step's 16 angles (hides L2/DRAM latency) ----
        float An[16];
        {
            int nwj = wj + 1, nwi = wi;
            if (nwj == 14) { nwj = 0; nwi++; }
            bool valid = (s + 1 < NSTEPS);
            int i2 = 2 * nwi, j2 = 2 * nwj;
            int hh = (i2 == 26) ? 2 : 4;
            int ww = (j2 == 26) ? 2 : 4;
            int hw = hh * ww;
            #pragma unroll
            for (int k = 0; k < 16; k++) {
                float v = 0.f;
                if (valid && k < hw) {
                    int r, c;
                    if (ww == 4) { r = k >> 2; c = k & 3; }
                    else         { r = k >> 1; c = k & 1; }
                    v = g_xT[((i2 + r) * 28 + (j2 + c)) * B_TOTAL + b];
                }
                An[k] = v;
            }
        }

        // ---- wires 0..2: U = RZ(a4) RY(a3) RZ(a2) RY(a1) RZ(a0) H ----
        #pragma unroll
        for (int w = 0; w < 3; w++) {
            float a0 = A[w * 5 + 0], a1 = A[w * 5 + 1], a2 = A[w * 5 + 2];
            float a3 = A[w * 5 + 3], a4 = A[w * 5 + 4];

            float c0 = __cosf(0.5f * a0), s0 = __sinf(0.5f * a0);
            // RZ(a0)*H
            float u00r = RS * c0, u00i = -RS * s0;
            float u01r = u00r,    u01i = u00i;
            float u10r = RS * c0, u10i = RS * s0;
            float u11r = -u10r,   u11i = -u10i;

            ry_left(__cosf(0.5f * a1), __sinf(0.5f * a1),
                    u00r, u00i, u01r, u01i, u10r, u10i, u11r, u11i);
            rz_left(__cosf(0.5f * a2), __sinf(0.5f * a2),
                    u00r, u00i, u01r, u01i, u10r, u10i, u11r, u11i);
            ry_left(__cosf(0.5f * a3), __sinf(0.5f * a3),
                    u00r, u00i, u01r, u01i, u10r, u10i, u11r, u11i);
            rz_left(__cosf(0.5f * a4), __sinf(0.5f * a4),
                    u00r, u00i, u01r, u01i, u10r, u10i, u11r, u11i);

            // apply U on wire w (bit 3-w, stride S)
            const int S = 8 >> w;
            #pragma unroll
            for (int g = 0; g < 8; g++) {
                int i0 = ((g & ~(S - 1)) << 1) | (g & (S - 1));
                int i1 = i0 + S;
                float x0r = Sr[i0], x0i = Si[i0], x1r = Sr[i1], x1i = Si[i1];
                Sr[i0] = u00r * x0r - u00i * x0i + u01r * x1r - u01i * x1i;
                Si[i0] = u00r * x0i + u00i * x0r + u01r * x1i + u01i * x1r;
                Sr[i1] = u10r * x0r - u10i * x0i + u11r * x1r - u11i * x1i;
                Si[i1] = u10r * x0i + u10i * x0r + u11r * x1i + u11i * x1r;
            }
        }

        // ---- wire 3: U = RZ(A15)*H (special form: butterfly + diag scale) ----
        {
            float c = __cosf(0.5f * A[15]), sn = __sinf(0.5f * A[15]);
            float emr = RS * c, emi = -RS * sn;
            float epr = RS * c, epi = RS * sn;
            #pragma unroll
            for (int g = 0; g < 8; g++) {
                int i0 = 2 * g, i1 = 2 * g + 1;
                float t0r = Sr[i0] + Sr[i1], t0i = Si[i0] + Si[i1];
                float t1r = Sr[i0] - Sr[i1], t1i = Si[i0] - Si[i1];
                Sr[i0] = emr * t0r - emi * t0i; Si[i0] = emr * t0i + emi * t0r;
                Sr[i1] = epr * t1r - epi * t1i; Si[i1] = epr * t1i + epi * t1r;
            }
        }

        // ---- CRZ diagonal ----
        #pragma unroll
        for (int n = 0; n < 16; n++) {
            float r_  = Sr[n] * crzr[n] - Si[n] * crzi[n];
            Si[n]     = Sr[n] * crzi[n] + Si[n] * crzr[n];
            Sr[n]     = r_;
        }

        // ---- Ry(ry_theta) on all 4 wires (real rotation) ----
        #pragma unroll
        for (int w = 0; w < 4; w++) {
            const int S = 8 >> w;
            #pragma unroll
            for (int g = 0; g < 8; g++) {
                int i0 = ((g & ~(S - 1)) << 1) | (g & (S - 1));
                int i1 = i0 + S;
                float x0r = Sr[i0], x0i = Si[i0], x1r = Sr[i1], x1i = Si[i1];
                Sr[i0] = cR * x0r - sR * x1r; Si[i0] = cR * x0i - sR * x1i;
                Sr[i1] = sR * x0r + cR * x1r; Si[i1] = sR * x0i + cR * x1i;
            }
        }

        // ---- probs + Z expectations via butterfly reduction ----
        float p[16];
        #pragma unroll
        for (int n = 0; n < 16; n++) p[n] = Sr[n] * Sr[n] + Si[n] * Si[n];
        float t8[8], e3 = 0.f;
        #pragma unroll
        for (int g = 0; g < 8; g++) { t8[g] = p[2*g] + p[2*g+1]; e3 += p[2*g] - p[2*g+1]; }
        float t4[4], e2 = 0.f;
        #pragma unroll
        for (int g = 0; g < 4; g++) { t4[g] = t8[2*g] + t8[2*g+1]; e2 += t8[2*g] - t8[2*g+1]; }
        float t2[2], e1 = 0.f;
        #pragma unroll
        for (int g = 0; g < 2; g++) { t2[g] = t4[2*g] + t4[2*g+1]; e1 += t4[2*g] - t4[2*g+1]; }
        float e0 = t2[0] - t2[1];

        // ---- fused fc1: h1[o] += sum_w e_w * W[(s*4+w)*20 + o] ----
        {
            const float4* w4 = (const float4*)(g_w1T + s * 80);
            float ev[4] = {e0, e1, e2, e3};
            #pragma unroll
            for (int w = 0; w < 4; w++) {
                #pragma unroll
                for (int q = 0; q < 5; q++) {
                    float4 ww = __ldg(&w4[w * 5 + q]);
                    h1[q * 4 + 0] += ev[w] * ww.x;
                    h1[q * 4 + 1] += ev[w] * ww.y;
                    h1[q * 4 + 2] += ev[w] * ww.z;
                    h1[q * 4 + 3] += ev[w] * ww.w;
                }
            }
        }

        // rotate prefetched angles in
        #pragma unroll
        for (int k = 0; k < 16; k++) A[k] = An[k];
        wj++; if (wj == 14) { wj = 0; wi++; }
    }

    // ---- leaky relu + fc2 ----
    float o0 = __ldg(&fc2_b[0]), o1 = __ldg(&fc2_b[1]);
    #pragma unroll
    for (int o = 0; o < 20; o++) {
        float h = h1[o];
        h = (h > 0.f) ? h : 0.1f * h;
        o0 += h * __ldg(&fc2_w[o]);
        o1 += h * __ldg(&fc2_w[20 + o]);
    }
    out[b * 2 + 0] = o0;
    out[b * 2 + 1] = o1;
}

// ---------------------------------------------------------------------------
// Launch
// ---------------------------------------------------------------------------
extern "C" void kernel_launch(void* const* d_in, const int* in_sizes, int n_in,
                              void* d_out, int out_size) {
    const float* x      = (const float*)d_in[0];
    const float* crz_t  = (const float*)d_in[1];
    const float* ry_t   = (const float*)d_in[2];
    const float* fc1_w  = (const float*)d_in[3];
    const float* fc1_b  = (const float*)d_in[4];
    const float* fc2_w  = (const float*)d_in[5];
    const float* fc2_b  = (const float*)d_in[6];
    float* out = (float*)d_out;

    dim3 tb(32, 8);
    dim3 tg(B_TOTAL / 32, (784 + 31) / 32);
    transpose_kernel<<<tg, tb>>>(x);

    w1t_kernel<<<(784 * 20 + 255) / 256, 256>>>(fc1_w);

    quanv_kernel<<<B_TOTAL / 128, 128>>>(crz_t, ry_t, fc1_b, fc2_w, fc2_b, out);
}

// round 3
// speedup vs baseline: 1.0091x; 1.0091x over previous
#include <cuda_runtime.h>

#define B_TOTAL 16384
#define NSTEPS  196

// Scratch (allocation-free: __device__ globals)
__device__ float g_xT[784 * B_TOTAL];   // transposed input: [pixel][batch]
__device__ float g_w1T[NSTEPS * 4 * 20]; // fc1 weights relaid: [(s*4+w)*20 + o]

// ---------------------------------------------------------------------------
// Kernel 1: transpose x (B,784) -> xT (784,B), coalesced both sides
// ---------------------------------------------------------------------------
__global__ void transpose_kernel(const float* __restrict__ x) {
    __shared__ float tile[32][33];
    const int bBase = blockIdx.x * 32;
    const int pBase = blockIdx.y * 32;
    const int tx = threadIdx.x, ty = threadIdx.y;
    #pragma unroll
    for (int k = 0; k < 4; k++) {
        int bb = bBase + ty + k * 8;
        int pp = pBase + tx;
        float v = 0.f;
        if (pp < 784) v = x[bb * 784 + pp];
        tile[ty + k * 8][tx] = v;
    }
    __syncthreads();
    #pragma unroll
    for (int k = 0; k < 4; k++) {
        int pp = pBase + ty + k * 8;
        int bb = bBase + tx;
        if (pp < 784) g_xT[pp * B_TOTAL + bb] = tile[tx][ty + k * 8];
    }
}

// ---------------------------------------------------------------------------
// Kernel 2: relay fc1_w (20,784) -> g_w1T[p*20+o] = fc1_w[o*784+p]
// ---------------------------------------------------------------------------
__global__ void w1t_kernel(const float* __restrict__ fc1_w) {
    int idx = blockIdx.x * blockDim.x + threadIdx.x;
    if (idx < 784 * 20) {
        int p = idx / 20, o = idx % 20;
        g_w1T[idx] = fc1_w[o * 784 + p];
    }
}

// ---------------------------------------------------------------------------
// Helpers: left-multiply 2x2 complex U by RY / RZ
// ---------------------------------------------------------------------------
__device__ __forceinline__ void ry_left(float c, float sn,
    float& u00r, float& u00i, float& u01r, float& u01i,
    float& u10r, float& u10i, float& u11r, float& u11i)
{
    float n00r = c * u00r - sn * u10r, n00i = c * u00i - sn * u10i;
    float n01r = c * u01r - sn * u11r, n01i = c * u01i - sn * u11i;
    float n10r = sn * u00r + c * u10r, n10i = sn * u00i + c * u10i;
    float n11r = sn * u01r + c * u11r, n11i = sn * u01i + c * u11i;
    u00r = n00r; u00i = n00i; u01r = n01r; u01i = n01i;
    u10r = n10r; u10i = n10i; u11r = n11r; u11i = n11i;
}

__device__ __forceinline__ void rz_left(float c, float sn,
    float& u00r, float& u00i, float& u01r, float& u01i,
    float& u10r, float& u10i, float& u11r, float& u11i)
{
    // row0 *= (c - i s); row1 *= (c + i s)
    float r_;
    r_ = c * u00r + sn * u00i; u00i = c * u00i - sn * u00r; u00r = r_;
    r_ = c * u01r + sn * u01i; u01i = c * u01i - sn * u01r; u01r = r_;
    r_ = c * u10r - sn * u10i; u10i = c * u10i + sn * u10r; u10r = r_;
    r_ = c * u11r - sn * u11i; u11i = c * u11i + sn * u11r; u11r = r_;
}

// ---------------------------------------------------------------------------
// Main kernel: one thread per batch element; state in registers.
// ---------------------------------------------------------------------------
__global__ __launch_bounds__(128, 1) void quanv_kernel(
    const float* __restrict__ crz_p, const float* __restrict__ ry_p,
    const float* __restrict__ fc1_b, const float* __restrict__ fc2_w,
    const float* __restrict__ fc2_b, float* __restrict__ out)
{
    const int b = blockIdx.x * 128 + threadIdx.x;
    const float RS = 0.7071067811865476f;

    // CRZ diagonal: exp(+0.5i * theta * sign[n]), sign from the ring pattern
    float crzr[16], crzi[16];
    {
        float th = __ldg(crz_p);
        #pragma unroll
        for (int n = 0; n < 16; n++) {
            int q0 = (n >> 3) & 1, q1 = (n >> 2) & 1, q2 = (n >> 1) & 1, q3 = n & 1;
            int sgn = q0 * (2 * q1 - 1) + q1 * (2 * q2 - 1)
                    + q2 * (2 * q3 - 1) + q3 * (2 * q0 - 1);
            float ang = 0.5f * th * (float)sgn;
            crzr[n] = __cosf(ang);
            crzi[n] = __sinf(ang);
        }
    }
    float ryt = __ldg(ry_p);
    const float cR = __cosf(0.5f * ryt), sR = __sinf(0.5f * ryt);

    // State |0000> ; carried across all 196 steps (lax.scan semantics)
    float Sr[16], Si[16];
    #pragma unroll
    for (int n = 0; n < 16; n++) { Sr[n] = 0.f; Si[n] = 0.f; }
    Sr[0] = 1.f;

    // Fused fc1 accumulators
    float h1[20];
    #pragma unroll
    for (int o = 0; o < 20; o++) h1[o] = __ldg(&fc1_b[o]);

    // Prefetch angles for step 0 (window i=0,j=0: full 4x4)
    float A[16];
    #pragma unroll
    for (int k = 0; k < 16; k++) {
        int r = k >> 2, c = k & 3;
        A[k] = g_xT[(r * 28 + c) * B_TOTAL + b];
    }

    int wi = 0, wj = 0;
    #pragma unroll 1
    for (int s = 0; s < NSTEPS; s++) {
        // ---- prefetch next step's 16 angles (hides L2/DRAM latency) ----
        float An[16];
        {
            int nwj = wj + 1, nwi = wi;
            if (nwj == 14) { nwj = 0; nwi++; }
            bool valid = (s + 1 < NSTEPS);
            int i2 = 2 * nwi, j2 = 2 * nwj;
            int hh = (i2 == 26) ? 2 : 4;
            int ww = (j2 == 26) ? 2 : 4;
            int hw = hh * ww;
            #pragma unroll
            for (int k = 0; k < 16; k++) {
                float v = 0.f;
                if (valid && k < hw) {
                    int r, c;
                    if (ww == 4) { r = k >> 2; c = k & 3; }
                    else         { r = k >> 1; c = k & 1; }
                    v = g_xT[((i2 + r) * 28 + (j2 + c)) * B_TOTAL + b];
                }
                An[k] = v;
            }
        }

        // ---- wires 0..2: U = RZ(a4) RY(a3) RZ(a2) RY(a1) RZ(a0) H ----
        #pragma unroll
        for (int w = 0; w < 3; w++) {
            float a0 = A[w * 5 + 0], a1 = A[w * 5 + 1], a2 = A[w * 5 + 2];
            float a3 = A[w * 5 + 3], a4 = A[w * 5 + 4];

            float c0 = __cosf(0.5f * a0), s0 = __sinf(0.5f * a0);
            // RZ(a0)*H
            float u00r = RS * c0, u00i = -RS * s0;
            float u01r = u00r,    u01i = u00i;
            float u10r = RS * c0, u10i = RS * s0;
            float u11r = -u10r,   u11i = -u10i;

            ry_left(__cosf(0.5f * a1), __sinf(0.5f * a1),
                    u00r, u00i, u01r, u01i, u10r, u10i, u11r, u11i);
            rz_left(__cosf(0.5f * a2), __sinf(0.5f * a2),
                    u00r, u00i, u01r, u01i, u10r, u10i, u11r, u11i);
            ry_left(__cosf(0.5f * a3), __sinf(0.5f * a3),
                    u00r, u00i, u01r, u01i, u10r, u10i, u11r, u11i);
            rz_left(__cosf(0.5f * a4), __sinf(0.5f * a4),
                    u00r, u00i, u01r, u01i, u10r, u10i, u11r, u11i);

            // apply U on wire w (bit 3-w, stride S)
            const int S = 8 >> w;
            #pragma unroll
            for (int g = 0; g < 8; g++) {
                int i0 = ((g & ~(S - 1)) << 1) | (g & (S - 1));
                int i1 = i0 + S;
                float x0r = Sr[i0], x0i = Si[i0], x1r = Sr[i1], x1i = Si[i1];
                Sr[i0] = u00r * x0r - u00i * x0i + u01r * x1r - u01i * x1i;
                Si[i0] = u00r * x0i + u00i * x0r + u01r * x1i + u01i * x1r;
                Sr[i1] = u10r * x0r - u10i * x0i + u11r * x1r - u11i * x1i;
                Si[i1] = u10r * x0i + u10i * x0r + u11r * x1i + u11i * x1r;
            }
        }

        // ---- wire 3: U = RZ(A15)*H (special form: butterfly + diag scale) ----
        {
            float c = __cosf(0.5f * A[15]), sn = __sinf(0.5f * A[15]);
            float emr = RS * c, emi = -RS * sn;
            float epr = RS * c, epi = RS * sn;
            #pragma unroll
            for (int g = 0; g < 8; g++) {
                int i0 = 2 * g, i1 = 2 * g + 1;
                float t0r = Sr[i0] + Sr[i1], t0i = Si[i0] + Si[i1];
                float t1r = Sr[i0] - Sr[i1], t1i = Si[i0] - Si[i1];
                Sr[i0] = emr * t0r - emi * t0i; Si[i0] = emr * t0i + emi * t0r;
                Sr[i1] = epr * t1r - epi * t1i; Si[i1] = epr * t1i + epi * t1r;
            }
        }

        // ---- CRZ diagonal ----
        #pragma unroll
        for (int n = 0; n < 16; n++) {
            float r_  = Sr[n] * crzr[n] - Si[n] * crzi[n];
            Si[n]     = Sr[n] * crzi[n] + Si[n] * crzr[n];
            Sr[n]     = r_;
        }

        // ---- Ry(ry_theta) on all 4 wires (real rotation) ----
        #pragma unroll
        for (int w = 0; w < 4; w++) {
            const int S = 8 >> w;
            #pragma unroll
            for (int g = 0; g < 8; g++) {
                int i0 = ((g & ~(S - 1)) << 1) | (g & (S - 1));
                int i1 = i0 + S;
                float x0r = Sr[i0], x0i = Si[i0], x1r = Sr[i1], x1i = Si[i1];
                Sr[i0] = cR * x0r - sR * x1r; Si[i0] = cR * x0i - sR * x1i;
                Sr[i1] = sR * x0r + cR * x1r; Si[i1] = sR * x0i + cR * x1i;
            }
        }

        // ---- probs + Z expectations via butterfly reduction ----
        float p[16];
        #pragma unroll
        for (int n = 0; n < 16; n++) p[n] = Sr[n] * Sr[n] + Si[n] * Si[n];
        float t8[8], e3 = 0.f;
        #pragma unroll
        for (int g = 0; g < 8; g++) { t8[g] = p[2*g] + p[2*g+1]; e3 += p[2*g] - p[2*g+1]; }
        float t4[4], e2 = 0.f;
        #pragma unroll
        for (int g = 0; g < 4; g++) { t4[g] = t8[2*g] + t8[2*g+1]; e2 += t8[2*g] - t8[2*g+1]; }
        float t2[2], e1 = 0.f;
        #pragma unroll
        for (int g = 0; g < 2; g++) { t2[g] = t4[2*g] + t4[2*g+1]; e1 += t4[2*g] - t4[2*g+1]; }
        float e0 = t2[0] - t2[1];

        // ---- fused fc1: h1[o] += sum_w e_w * W[(s*4+w)*20 + o] ----
        {
            const float4* w4 = (const float4*)(g_w1T + s * 80);
            float ev[4] = {e0, e1, e2, e3};
            #pragma unroll
            for (int w = 0; w < 4; w++) {
                #pragma unroll
                for (int q = 0; q < 5; q++) {
                    float4 ww = __ldg(&w4[w * 5 + q]);
                    h1[q * 4 + 0] += ev[w] * ww.x;
                    h1[q * 4 + 1] += ev[w] * ww.y;
                    h1[q * 4 + 2] += ev[w] * ww.z;
                    h1[q * 4 + 3] += ev[w] * ww.w;
                }
            }
        }

        // rotate prefetched angles in
        #pragma unroll
        for (int k = 0; k < 16; k++) A[k] = An[k];
        wj++; if (wj == 14) { wj = 0; wi++; }
    }

    // ---- leaky relu + fc2 ----
    float o0 = __ldg(&fc2_b[0]), o1 = __ldg(&fc2_b[1]);
    #pragma unroll
    for (int o = 0; o < 20; o++) {
        float h = h1[o];
        h = (h > 0.f) ? h : 0.1f * h;
        o0 += h * __ldg(&fc2_w[o]);
        o1 += h * __ldg(&fc2_w[20 + o]);
    }
    out[b * 2 + 0] = o0;
    out[b * 2 + 1] = o1;
}

// ---------------------------------------------------------------------------
// Launch
// ---------------------------------------------------------------------------
extern "C" void kernel_launch(void* const* d_in, const int* in_sizes, int n_in,
                              void* d_out, int out_size) {
    const float* x      = (const float*)d_in[0];
    const float* crz_t  = (const float*)d_in[1];
    const float* ry_t   = (const float*)d_in[2];
    const float* fc1_w  = (const float*)d_in[3];
    const float* fc1_b  = (const float*)d_in[4];
    const float* fc2_w  = (const float*)d_in[5];
    const float* fc2_b  = (const float*)d_in[6];
    float* out = (float*)d_out;

    dim3 tb(32, 8);
    dim3 tg(B_TOTAL / 32, (784 + 31) / 32);
    transpose_kernel<<<tg, tb>>>(x);

    w1t_kernel<<<(784 * 20 + 255) / 256, 256>>>(fc1_w);

    quanv_kernel<<<B_TOTAL / 128, 128>>>(crz_t, ry_t, fc1_b, fc2_w, fc2_b, out);
}